// round 1
// baseline (speedup 1.0000x reference)
#include <cuda_runtime.h>
#include <math.h>
#include <stdint.h>

#define SCALE_MIN_C 1e-05f
#define SCALE_RANGE_C (30.0f - 1e-05f)
#define EPS_C 1e-08f
#define NPARAM 32
#define MAX_BV 256

// Param layout per (b,v):
// [0..8]   Rc2w (row-major)
// [9..11]  origin
// [12..20] Kinv (of normalized intrinsics)
// [21..24] c2w quaternion (w,x,y,z)
// [25]     mult (scale multiplier)
// [26]     1/W
// [27]     1/H
__device__ float g_params[MAX_BV * NPARAM];

__global__ void precompute_kernel(const float* __restrict__ ext,
                                  const float* __restrict__ intr,
                                  const int* __restrict__ Hp,
                                  const int* __restrict__ Wp,
                                  int BV) {
    int i = blockIdx.x * blockDim.x + threadIdx.x;
    if (i >= BV || i >= MAX_BV) return;
    float Wf = Wp ? (float)__ldg(Wp) : 384.0f;
    float Hf = Hp ? (float)__ldg(Hp) : 256.0f;

    const float* E = ext + (size_t)i * 16;
    // Rc2w = Rw2c^T
    float R0 = E[0], R1 = E[4], R2 = E[8];
    float R3 = E[1], R4 = E[5], R5 = E[9];
    float R6 = E[2], R7 = E[6], R8 = E[10];
    float t0 = E[3], t1 = E[7], t2 = E[11];

    float* P = g_params + i * NPARAM;
    P[0] = R0; P[1] = R1; P[2] = R2;
    P[3] = R3; P[4] = R4; P[5] = R5;
    P[6] = R6; P[7] = R7; P[8] = R8;
    P[9]  = -(R0 * t0 + R1 * t1 + R2 * t2);
    P[10] = -(R3 * t0 + R4 * t1 + R5 * t2);
    P[11] = -(R6 * t0 + R7 * t1 + R8 * t2);

    // Normalized intrinsics: rows scaled by [1/W, 1/H, 1]
    const float* K = intr + (size_t)i * 9;
    float a0 = K[0] / Wf, a1 = K[1] / Wf, a2 = K[2] / Wf;
    float a3 = K[3] / Hf, a4 = K[4] / Hf, a5 = K[5] / Hf;
    float a6 = K[6],      a7 = K[7],      a8 = K[8];

    // General 3x3 inverse (cofactors)
    float c00 = a4 * a8 - a5 * a7, c01 = a2 * a7 - a1 * a8, c02 = a1 * a5 - a2 * a4;
    float c10 = a5 * a6 - a3 * a8, c11 = a0 * a8 - a2 * a6, c12 = a2 * a3 - a0 * a5;
    float c20 = a3 * a7 - a4 * a6, c21 = a1 * a6 - a0 * a7, c22 = a0 * a4 - a1 * a3;
    float det = a0 * c00 + a1 * c10 + a2 * c20;
    float id = 1.0f / det;
    P[12] = c00 * id; P[13] = c01 * id; P[14] = c02 * id;
    P[15] = c10 * id; P[16] = c11 * id; P[17] = c12 * id;
    P[18] = c20 * id; P[19] = c21 * id; P[20] = c22 * id;

    // mult = 0.1 * sum_i (inv2 @ pixel_size)_i, inv2 = inverse of a[:2,:2]
    float det2 = a0 * a4 - a1 * a3;
    float psx = 1.0f / Wf, psy = 1.0f / Hf;
    float m0 = (a4 * psx - a1 * psy) / det2;
    float m1 = (-a3 * psx + a0 * psy) / det2;
    P[25] = 0.1f * (m0 + m1);

    // Quaternion (wxyz) of Rc2w, matching _mat_to_quat_wxyz
    float m00 = R0, m01 = R1, m02 = R2;
    float m10 = R3, m11 = R4, m12 = R5;
    float m20 = R6, m21 = R7, m22 = R8;
    float qa0 = sqrtf(fmaxf(0.f, 1.f + m00 + m11 + m22));
    float qa1 = sqrtf(fmaxf(0.f, 1.f + m00 - m11 - m22));
    float qa2 = sqrtf(fmaxf(0.f, 1.f - m00 + m11 - m22));
    float qa3 = sqrtf(fmaxf(0.f, 1.f - m00 - m11 + m22));
    int idx = 0; float best = qa0;
    if (qa1 > best) { best = qa1; idx = 1; }
    if (qa2 > best) { best = qa2; idx = 2; }
    if (qa3 > best) { best = qa3; idx = 3; }
    float c0, c1, c2, c3;
    if (idx == 0)      { c0 = qa0 * qa0;  c1 = m21 - m12;  c2 = m02 - m20;  c3 = m10 - m01; }
    else if (idx == 1) { c0 = m21 - m12;  c1 = qa1 * qa1;  c2 = m10 + m01;  c3 = m02 + m20; }
    else if (idx == 2) { c0 = m02 - m20;  c1 = m10 + m01;  c2 = qa2 * qa2;  c3 = m12 + m21; }
    else               { c0 = m10 - m01;  c1 = m20 + m02;  c2 = m21 + m12;  c3 = qa3 * qa3; }
    float den = 2.0f * fmaxf(best, 0.1f);
    c0 /= den; c1 /= den; c2 /= den; c3 /= den;
    float qn = rsqrtf(c0 * c0 + c1 * c1 + c2 * c2 + c3 * c3);
    P[21] = c0 * qn; P[22] = c1 * qn; P[23] = c2 * qn; P[24] = c3 * qn;

    P[26] = 1.0f / Wf;
    P[27] = 1.0f / Hf;
    P[28] = 0.f; P[29] = 0.f; P[30] = 0.f; P[31] = 0.f;
}

__device__ __forceinline__ float sigmoidf_(float x) {
    return 1.0f / (1.0f + __expf(-x));
}

__device__ __forceinline__ void compute_one(
    const float* P, int g, int h, int w,
    const float* __restrict__ depths, const float* __restrict__ opacs,
    const float* __restrict__ raw, float* __restrict__ out, size_t T)
{
    const float4* rp = reinterpret_cast<const float4*>(raw) + (size_t)g * 3;
    float4 r0 = __ldg(rp + 0);
    float4 r1 = __ldg(rp + 1);
    float4 r2 = __ldg(rp + 2);
    float depth = __ldg(depths + g);
    float op = __ldg(opacs + g);

    float invW = P[26], invH = P[27];
    float x = ((float)w + 0.5f + r0.x) * invW;
    float y = ((float)h + 0.5f + r0.y) * invH;

    // d_cam = Kinv @ [x, y, 1], normalized
    float dx = P[12] * x + P[13] * y + P[14];
    float dy = P[15] * x + P[16] * y + P[17];
    float dz = P[18] * x + P[19] * y + P[20];
    float rn = rsqrtf(dx * dx + dy * dy + dz * dz);
    dx *= rn; dy *= rn; dz *= rn;

    // d_world = Rc2w @ d_cam; mean = origin + d_world * depth
    float wx = P[0] * dx + P[1] * dy + P[2] * dz;
    float wy = P[3] * dx + P[4] * dy + P[5] * dz;
    float wz = P[6] * dx + P[7] * dy + P[8] * dz;
    float mx = P[9]  + wx * depth;
    float my = P[10] + wy * depth;
    float mz = P[11] + wz * depth;

    // scales
    float sm = depth * P[25];
    float s0 = (SCALE_MIN_C + SCALE_RANGE_C * sigmoidf_(r0.z)) * sm;
    float s1 = (SCALE_MIN_C + SCALE_RANGE_C * sigmoidf_(r0.w)) * sm;
    float s2 = (SCALE_MIN_C + SCALE_RANGE_C * sigmoidf_(r1.x)) * sm;

    // rotation: raw[5:9] = (r1.y, r1.z, r1.w, r2.x) as xyzw; cam_q = (w,x,y,z)
    float nrm = sqrtf(r1.y * r1.y + r1.z * r1.z + r1.w * r1.w + r2.x * r2.x) + EPS_C;
    float in = 1.0f / nrm;
    float bw = r2.x * in, bx = r1.y * in, by = r1.z * in, bz = r1.w * in;
    float aw = P[21], ax = P[22], ay = P[23], az = P[24];
    float qw = aw * bw - ax * bx - ay * by - az * bz;
    float qx = aw * bx + ax * bw + ay * bz - az * by;
    float qy = aw * by - ax * bz + ay * bw + az * bx;
    float qz = aw * bz + ax * by - ay * bx + az * bw;

    // writes: [means 3T][scales 3T][rot 4T][harm 3T][opac T]
    size_t g3 = (size_t)g * 3;
    out[g3] = mx; out[g3 + 1] = my; out[g3 + 2] = mz;
    float* so = out + 3 * T;
    so[g3] = s0; so[g3 + 1] = s1; so[g3 + 2] = s2;
    float* ro = out + 6 * T;
    if ((((uintptr_t)ro) & 15) == 0) {
        reinterpret_cast<float4*>(ro)[g] = make_float4(qw, qx, qy, qz);
    } else {
        size_t g4 = (size_t)g * 4;
        ro[g4] = qw; ro[g4 + 1] = qx; ro[g4 + 2] = qy; ro[g4 + 3] = qz;
    }
    float* ho = out + 10 * T;
    ho[g3] = r2.y; ho[g3 + 1] = r2.z; ho[g3 + 2] = r2.w;
    out[13 * T + (size_t)g] = op;
}

// Fast path: every block lies entirely within one (b,v) view (HW % blockDim == 0)
__global__ void __launch_bounds__(256) adapter_uniform_kernel(
    const float* __restrict__ depths, const float* __restrict__ opacs,
    const float* __restrict__ raw, const int* __restrict__ Wp,
    float* __restrict__ out, int total, int HW)
{
    __shared__ float sp[NPARAM];
    int base = blockIdx.x * blockDim.x;
    int bv = base / HW;
    if (threadIdx.x < NPARAM) sp[threadIdx.x] = g_params[bv * NPARAM + threadIdx.x];
    __syncthreads();
    int g = base + threadIdx.x;
    if (g >= total) return;
    int W = Wp ? __ldg(Wp) : 384;
    int rem = g - bv * HW;
    int h = rem / W;
    int w = rem - h * W;
    compute_one(sp, g, h, w, depths, opacs, raw, out, (size_t)total);
}

// General fallback: per-thread view lookup from global params
__global__ void __launch_bounds__(256) adapter_general_kernel(
    const float* __restrict__ depths, const float* __restrict__ opacs,
    const float* __restrict__ raw, const int* __restrict__ Wp,
    float* __restrict__ out, int total, int HW)
{
    int g = blockIdx.x * blockDim.x + threadIdx.x;
    if (g >= total) return;
    int W = Wp ? __ldg(Wp) : 384;
    int bv = g / HW;
    int rem = g - bv * HW;
    int h = rem / W;
    int w = rem - h * W;
    compute_one(g_params + bv * NPARAM, g, h, w, depths, opacs, raw, out, (size_t)total);
}

extern "C" void kernel_launch(void* const* d_in, const int* in_sizes, int n_in,
                              void* d_out, int out_size) {
    const float* ext    = (const float*)d_in[0];   // (B,V,4,4)
    const float* intr   = (const float*)d_in[1];   // (B,V,3,3)
    const float* depths = (const float*)d_in[2];   // (B,V,H,W)
    const float* opacs  = (const float*)d_in[3];   // (B,V,H,W)
    const float* raw    = (const float*)d_in[4];   // (B,V,H,W,12)
    const int* Hp = (n_in > 5) ? (const int*)d_in[5] : nullptr;
    const int* Wp = (n_in > 6) ? (const int*)d_in[6] : nullptr;

    int total = in_sizes[2];          // B*V*H*W
    int BV = in_sizes[0] / 16;        // B*V
    if (BV < 1) BV = 1;
    int HW = total / BV;              // H*W
    float* out = (float*)d_out;
    (void)out_size;

    precompute_kernel<<<1, 256>>>(ext, intr, Hp, Wp, BV);

    const int threads = 256;
    if ((HW % threads) == 0) {
        int blocks = total / threads;
        adapter_uniform_kernel<<<blocks, threads>>>(depths, opacs, raw, Wp, out, total, HW);
    } else {
        int blocks = (total + threads - 1) / threads;
        adapter_general_kernel<<<blocks, threads>>>(depths, opacs, raw, Wp, out, total, HW);
    }
}